// round 12
// baseline (speedup 1.0000x reference)
#include <cuda_runtime.h>
#include <cuda_bf16.h>
#include <cuda_fp16.h>
#include <math.h>
#include <stdint.h>

// Problem constants
#define NB 2
#define NS 2048
#define NHID 4096
#define NHEADS 32
#define HDIM 128
#define NQKV 12288   // 3*NHID
#define MTOK 4096    // NB*NS

// Scratch (device globals: allocation-free per harness rules)
__device__ __half g_qkv[(size_t)MTOK * NQKV];              // fp16; V read in-place
__device__ __half g_q16[(size_t)NB * NHEADS * NS * HDIM];  // head-major, q*scale*log2e
__device__ __half g_k16[(size_t)NB * NHEADS * NS * HDIM];
__device__ __half g_a16[(size_t)MTOK * NHID];              // GEMM A (fp16)
__device__ __half g_b16[(size_t)NQKV * NHID];              // GEMM B (fp16)

// ---------------------------------------------------------------------------
// Helpers (baseline PTX, valid on compute_100)
// ---------------------------------------------------------------------------
__device__ __forceinline__ uint32_t smem_u32(const void* p) {
    uint32_t a;
    asm("{ .reg .u64 t; cvta.to.shared.u64 t, %1; cvt.u32.u64 %0, t; }"
        : "=r"(a) : "l"(p));
    return a;
}

__device__ __forceinline__ void cp_async16(uint32_t dst, const void* src) {
    asm volatile("cp.async.cg.shared.global [%0], [%1], 16;" :: "r"(dst), "l"(src));
}
#define CP_COMMIT() asm volatile("cp.async.commit_group;" ::: "memory")

__device__ __forceinline__ void ldsm4(uint32_t* r, uint32_t addr) {
    asm volatile("ldmatrix.sync.aligned.m8n8.x4.shared.b16 {%0,%1,%2,%3}, [%4];"
                 : "=r"(r[0]), "=r"(r[1]), "=r"(r[2]), "=r"(r[3]) : "r"(addr));
}
__device__ __forceinline__ void ldsm4t(uint32_t* r, uint32_t addr) {
    asm volatile("ldmatrix.sync.aligned.m8n8.x4.trans.shared.b16 {%0,%1,%2,%3}, [%4];"
                 : "=r"(r[0]), "=r"(r[1]), "=r"(r[2]), "=r"(r[3]) : "r"(addr));
}

__device__ __forceinline__ void mma16816h(float* c, const uint32_t* a,
                                          uint32_t b0, uint32_t b1) {  // fp16
    asm volatile(
        "mma.sync.aligned.m16n8k16.row.col.f32.f16.f16.f32 "
        "{%0,%1,%2,%3}, {%4,%5,%6,%7}, {%8,%9}, {%0,%1,%2,%3};"
        : "+f"(c[0]), "+f"(c[1]), "+f"(c[2]), "+f"(c[3])
        : "r"(a[0]), "r"(a[1]), "r"(a[2]), "r"(a[3]), "r"(b0), "r"(b1));
}

#define SWZ(x) ((x) ^ (((x) >> 3) & 0x70))

__device__ __forceinline__ uint32_t pack_f16(float x, float y) {
    __half2 t = __floats2half2_rn(x, y);
    return *(uint32_t*)&t;
}

// ---------------------------------------------------------------------------
// convert: fp32 -> fp16
// ---------------------------------------------------------------------------
__global__ __launch_bounds__(256) void conv_f16(
    const float* __restrict__ x, __half* __restrict__ o)
{
    size_t i = ((size_t)blockIdx.x * 256 + threadIdx.x) * 4;
    float4 v = *(const float4*)(x + i);
    uint2 r;
    r.x = pack_f16(v.x, v.y);
    r.y = pack_f16(v.z, v.w);
    *(uint2*)(o + i) = r;
}

// ---------------------------------------------------------------------------
// fp16 GEMM (NT): C[m,n] = sum_k A[m,k]*B[n,k]
// CTA tile 128x256, 8 warps (2m x 4n), warp tile 64x64, KTILE=64,
// 3-stage cp.async, 1 CTA/SM. AI = 87 FLOP/byte (was 64) -> 26% less L2 feed.
// ---------------------------------------------------------------------------
#define FKT 64
#define FABUF 16384                 // A: 128 rows x 128 B
#define FBBUF 32768                 // B: 256 rows x 128 B
#define FSTG (FABUF + FBBUF)        // 48 KB per stage
#define GEMM_SMEM (3 * FSTG)        // 144 KB

template <typename OutT>
__global__ __launch_bounds__(256, 1) void gemm_f16(
    const __half* __restrict__ A, const __half* __restrict__ B,
    OutT* __restrict__ C, int M, int N, int K)
{
    extern __shared__ char smem[];
    const uint32_t sbase = smem_u32(smem);

    const int tid  = threadIdx.x;
    const int lane = tid & 31;
    const int wid  = tid >> 5;
    const int wm   = wid >> 2;          // 0..1 (64-row slab)
    const int wn   = wid & 3;           // 0..3 (64-col slab)
    const int m0   = blockIdx.x * 128;
    const int n0   = blockIdx.y * 256;

    auto load_stage = [&](int kt) {
        const int kk = kt * FKT;
        const uint32_t su = sbase + (kt % 3) * FSTG;
#pragma unroll
        for (int i = 0; i < 12; i++) {
            int c = tid + 256 * i;          // 0..3071
            if (c < 1024) {                 // A: 128 rows x 8 chunks
                int r = c >> 3, ch = c & 7;
                uint32_t dst = su + SWZ((uint32_t)(r * 128 + ch * 16));
                cp_async16(dst, A + (size_t)(m0 + r) * K + kk + ch * 8);
            } else {                        // B: 256 rows x 8 chunks
                int cb = c - 1024;
                int r = cb >> 3, ch = cb & 7;
                uint32_t dst = su + FABUF + SWZ((uint32_t)(r * 128 + ch * 16));
                cp_async16(dst, B + (size_t)(n0 + r) * K + kk + ch * 8);
            }
        }
        CP_COMMIT();
    };

    float acc[4][8][4];
#pragma unroll
    for (int i = 0; i < 4; i++)
#pragma unroll
        for (int j = 0; j < 8; j++)
#pragma unroll
            for (int v = 0; v < 4; v++) acc[i][j][v] = 0.f;

    const int KT = K / FKT;
    load_stage(0);
    load_stage(1);

    const int mat  = lane >> 3;
    const int rsub = (mat & 1) * 8 + (lane & 7);
    const int csub = mat >> 1;

    for (int kt = 0; kt < KT; kt++) {
        if (kt + 1 < KT) {
            asm volatile("cp.async.wait_group 1;" ::: "memory");
        } else {
            asm volatile("cp.async.wait_group 0;" ::: "memory");
        }
        __syncthreads();
        if (kt + 2 < KT) load_stage(kt + 2);  // ring: (kt+2)%3 == (kt-1)%3, safe

        const uint32_t Ab = sbase + (kt % 3) * FSTG;
        const uint32_t Bb = Ab + FABUF;

#pragma unroll
        for (int ks = 0; ks < 4; ks++) {
            uint32_t af[4][4], bf[4][4];
            const int chh = ks * 2 + csub;
#pragma unroll
            for (int mf = 0; mf < 4; mf++) {
                int r = wm * 64 + mf * 16 + rsub;
                ldsm4(af[mf], Ab + SWZ((uint32_t)(r * 128 + chh * 16)));
            }
#pragma unroll
            for (int nf2 = 0; nf2 < 4; nf2++) {
                int r = wn * 64 + nf2 * 16 + rsub;
                ldsm4(bf[nf2], Bb + SWZ((uint32_t)(r * 128 + chh * 16)));
            }
#pragma unroll
            for (int mf = 0; mf < 4; mf++)
#pragma unroll
                for (int nf = 0; nf < 8; nf++)
                    mma16816h(acc[mf][nf], af[mf],
                              bf[nf >> 1][nf & 1], bf[nf >> 1][(nf & 1) + 2]);
        }
    }

    const int gg = lane >> 2;
    const int tq = lane & 3;
#pragma unroll
    for (int mf = 0; mf < 4; mf++) {
#pragma unroll
        for (int nf = 0; nf < 8; nf++) {
            int row = m0 + wm * 64 + mf * 16 + gg;
            int col = n0 + wn * 64 + nf * 8 + tq * 2;
            if (sizeof(OutT) == 4) {
                *(float2*)((float*)C + (size_t)row * N + col) =
                    make_float2(acc[mf][nf][0], acc[mf][nf][1]);
                *(float2*)((float*)C + (size_t)(row + 8) * N + col) =
                    make_float2(acc[mf][nf][2], acc[mf][nf][3]);
            } else {
                *(uint32_t*)((__half*)C + (size_t)row * N + col) =
                    pack_f16(acc[mf][nf][0], acc[mf][nf][1]);
                *(uint32_t*)((__half*)C + (size_t)(row + 8) * N + col) =
                    pack_f16(acc[mf][nf][2], acc[mf][nf][3]);
            }
        }
    }
}

// ---------------------------------------------------------------------------
// RoPE (fp32 trig) + head-major fp16 q (pre-scaled by 1/sqrt(hd)*log2(e)), k.
// V stays in g_qkv. 128 threads = 2 (token,head) pairs.
// ---------------------------------------------------------------------------
__global__ __launch_bounds__(128) void rope_f16(
    const __half* __restrict__ qkv, const int* __restrict__ positions)
{
    int t  = threadIdx.x;
    int gi = blockIdx.x * 2 + (t >> 6);   // (b*NS+s)*NHEADS+h
    int d  = t & 63;
    int h  = gi % NHEADS;
    int ms = gi / NHEADS;
    int s  = ms % NS;
    int b  = ms / NS;

    const __half* row = qkv + (size_t)ms * NQKV + h * HDIM;
    const float qscale = 0.12751745f;     // 1/sqrt(128) * log2(e)

    float posf = (float)positions[ms];
    float invf = expf(-(float)d * (9.210340371976184f / 64.0f));  // ln(10000)/64
    float sn, cs;
    sincosf(posf * invf, &sn, &cs);

    float q1 = __half2float(row[d]),        q2 = __half2float(row[d + 64]);
    float k1 = __half2float(row[NHID + d]), k2 = __half2float(row[NHID + d + 64]);

    size_t o = ((size_t)((b * NHEADS + h)) * NS + s) * HDIM + d;
    g_q16[o]      = __float2half_rn((q1 * cs - q2 * sn) * qscale);
    g_q16[o + 64] = __float2half_rn((q2 * cs + q1 * sn) * qscale);
    g_k16[o]      = __float2half_rn(k1 * cs - k2 * sn);
    g_k16[o + 64] = __float2half_rn(k2 * cs + k1 * sn);
}

// ---------------------------------------------------------------------------
// Flash attention, all-fp16 HMMA single-pass. Logits are in log2 units (Q
// pre-scaled by log2e), so softmax uses raw exp2f (pure MUFU, no extra FMUL).
// CTA = 128 q-rows, 8 warps, 64-wide k chunks, 3-stage cp.async KV pipeline.
// V read directly from g_qkv (row stride NQKV). Heavy q-tiles first.
// ---------------------------------------------------------------------------
#define AQT 128
#define AKT 64
#define AKV 16384
#define ASTG (2 * AKV)                   // K | V per stage
#define ATTN_SMEM (32768 + 3 * ASTG)     // Q + 3 stages = 131072

__global__ __launch_bounds__(256, 1) void attn_mma()
{
    extern __shared__ char smem[];
    const uint32_t sQ = smem_u32(smem);
    const int tid  = threadIdx.x;
    const int lane = tid & 31;
    const int w    = tid >> 5;
    const int qt   = (int)gridDim.x - 1 - (int)blockIdx.x;  // heavy tiles first
    const int bh   = blockIdx.y;
    const int qs0  = qt * AQT;
    const size_t hb = (size_t)bh * NS * HDIM;
    const int b = bh >> 5, h = bh & 31;

    const int g  = lane >> 2;
    const int t2 = (lane & 3) * 2;
    const int lr = (lane & 7) + ((lane >> 3) & 1) * 8;
    const int lc = lane >> 4;

#pragma unroll
    for (int i = 0; i < 8; i++) {
        int idx = tid + 256 * i;
        int r = idx >> 4, c = idx & 15;
        uint32_t dst = sQ + r * 256 + ((c ^ (r & 7)) << 4);
        cp_async16(dst, g_q16 + hb + (size_t)(qs0 + r) * HDIM + c * 8);
    }
    auto load_kv = [&](int kt) {
        int kc0 = kt * AKT;
        uint32_t sb = sQ + 32768 + (kt % 3) * ASTG;
#pragma unroll
        for (int i = 0; i < 8; i++) {
            int idx = tid + 256 * i;             // 0..2047
            int buf = idx >> 10;                 // 0=K 1=V
            int rem = idx & 1023;
            int r = rem >> 4, c = rem & 15;
            uint32_t dst = sb + buf * AKV + r * 256 + ((c ^ (r & 7)) << 4);
            const void* src = buf == 0
                ? (const void*)(g_k16 + hb + (size_t)(kc0 + r) * HDIM + c * 8)
                : (const void*)(g_qkv + (size_t)(b * NS + kc0 + r) * NQKV
                                + 2 * NHID + h * HDIM + c * 8);
            cp_async16(dst, src);
        }
        CP_COMMIT();
    };

    const int KN = 2 * qt + 2;
    load_kv(0);
    load_kv(1);

    float oacc[16][4];
#pragma unroll
    for (int i = 0; i < 16; i++)
#pragma unroll
        for (int v = 0; v < 4; v++) oacc[i][v] = 0.f;
    float m0 = -INFINITY, m1 = -INFINITY, l0 = 0.f, l1 = 0.f;

    const int row0 = qs0 + w * 16 + g;

    for (int kt = 0; kt < KN; kt++) {
        if (kt + 1 < KN) {
            asm volatile("cp.async.wait_group 1;" ::: "memory");
        } else {
            asm volatile("cp.async.wait_group 0;" ::: "memory");
        }
        __syncthreads();
        if (kt + 2 < KN) load_kv(kt + 2);

        if (kt * AKT <= qs0 + w * 16 + 15) {
            const uint32_t sK = sQ + 32768 + (kt % 3) * ASTG;
            const uint32_t sV = sK + AKV;

            // ---- S = Q K^T (log2-scaled logits) ----
            float sacc[8][4];
#pragma unroll
            for (int nf = 0; nf < 8; nf++)
#pragma unroll
                for (int v = 0; v < 4; v++) sacc[nf][v] = 0.f;

#pragma unroll
            for (int ks = 0; ks < 8; ks++) {
                uint32_t aq[4];
                {
                    int r = w * 16 + lr, c = 2 * ks + lc;
                    ldsm4(aq, sQ + r * 256 + ((c ^ (r & 7)) << 4));
                }
                uint32_t kb4[4][4];
#pragma unroll
                for (int kg = 0; kg < 4; kg++) {
                    int r = kg * 16 + lr, c = 2 * ks + lc;
                    ldsm4(kb4[kg], sK + r * 256 + ((c ^ (r & 7)) << 4));
                }
#pragma unroll
                for (int nf = 0; nf < 8; nf++)
                    mma16816h(sacc[nf], aq, kb4[nf >> 1][nf & 1],
                              kb4[nf >> 1][(nf & 1) + 2]);
            }

            // ---- causal mask (diagonal chunks only) ----
            if (kt * AKT + 63 > qs0 + w * 16) {
#pragma unroll
                for (int nf = 0; nf < 8; nf++) {
                    int cb = kt * AKT + nf * 8 + t2;
                    if (cb     > row0)     sacc[nf][0] = -1e30f;
                    if (cb + 1 > row0)     sacc[nf][1] = -1e30f;
                    if (cb     > row0 + 8) sacc[nf][2] = -1e30f;
                    if (cb + 1 > row0 + 8) sacc[nf][3] = -1e30f;
                }
            }

            // ---- online softmax (base-2) ----
            float mx0 = -1e30f, mx1 = -1e30f;
#pragma unroll
            for (int nf = 0; nf < 8; nf++) {
                mx0 = fmaxf(mx0, fmaxf(sacc[nf][0], sacc[nf][1]));
                mx1 = fmaxf(mx1, fmaxf(sacc[nf][2], sacc[nf][3]));
            }
            mx0 = fmaxf(mx0, __shfl_xor_sync(0xffffffffu, mx0, 1));
            mx0 = fmaxf(mx0, __shfl_xor_sync(0xffffffffu, mx0, 2));
            mx1 = fmaxf(mx1, __shfl_xor_sync(0xffffffffu, mx1, 1));
            mx1 = fmaxf(mx1, __shfl_xor_sync(0xffffffffu, mx1, 2));

            float nm0 = fmaxf(m0, mx0), nm1 = fmaxf(m1, mx1);
            float cr0 = exp2f(m0 - nm0), cr1 = exp2f(m1 - nm1);
            m0 = nm0; m1 = nm1;
#pragma unroll
            for (int nf = 0; nf < 16; nf++) {
                oacc[nf][0] *= cr0; oacc[nf][1] *= cr0;
                oacc[nf][2] *= cr1; oacc[nf][3] *= cr1;
            }

            float rs0 = 0.f, rs1 = 0.f;
            uint32_t pf[4][4];
#pragma unroll
            for (int kg = 0; kg < 4; kg++) {
                float p[2][4];
#pragma unroll
                for (int j = 0; j < 2; j++) {
                    int nf = 2 * kg + j;
                    p[j][0] = exp2f(sacc[nf][0] - nm0);
                    p[j][1] = exp2f(sacc[nf][1] - nm0);
                    p[j][2] = exp2f(sacc[nf][2] - nm1);
                    p[j][3] = exp2f(sacc[nf][3] - nm1);
                    rs0 += p[j][0] + p[j][1];
                    rs1 += p[j][2] + p[j][3];
                }
                pf[kg][0] = pack_f16(p[0][0], p[0][1]);
                pf[kg][1] = pack_f16(p[0][2], p[0][3]);
                pf[kg][2] = pack_f16(p[1][0], p[1][1]);
                pf[kg][3] = pack_f16(p[1][2], p[1][3]);
            }
            rs0 += __shfl_xor_sync(0xffffffffu, rs0, 1);
            rs0 += __shfl_xor_sync(0xffffffffu, rs0, 2);
            rs1 += __shfl_xor_sync(0xffffffffu, rs1, 1);
            rs1 += __shfl_xor_sync(0xffffffffu, rs1, 2);
            l0 = l0 * cr0 + rs0;
            l1 = l1 * cr1 + rs1;

            // ---- O += P V (single fp16 pass) ----
#pragma unroll
            for (int dg = 0; dg < 8; dg++) {
#pragma unroll
                for (int kg = 0; kg < 4; kg++) {
                    int r = kg * 16 + lr, c = 2 * dg + lc;
                    uint32_t vv[4];
                    ldsm4t(vv, sV + (uint32_t)(r * 256 + ((c ^ (r & 7)) << 4)));
                    mma16816h(oacc[2 * dg],     pf[kg], vv[0], vv[1]);
                    mma16816h(oacc[2 * dg + 1], pf[kg], vv[2], vv[3]);
                }
            }
        }
        __syncthreads();
    }

    // epilogue: normalize, write fp16 into out-proj A buffer
    float inv0 = 1.f / l0, inv1 = 1.f / l1;
    size_t ob0 = (size_t)(b * NS + row0) * NHID + h * HDIM + t2;
    size_t ob1 = ob0 + (size_t)8 * NHID;
#pragma unroll
    for (int nf = 0; nf < 16; nf++) {
        *(uint32_t*)(g_a16 + ob0 + nf * 8) =
            pack_f16(oacc[nf][0] * inv0, oacc[nf][1] * inv0);
        *(uint32_t*)(g_a16 + ob1 + nf * 8) =
            pack_f16(oacc[nf][2] * inv1, oacc[nf][3] * inv1);
    }
}

// ---------------------------------------------------------------------------
// Launch
// ---------------------------------------------------------------------------
extern "C" void kernel_launch(void* const* d_in, const int* in_sizes, int n_in,
                              void* d_out, int out_size)
{
    const float* hs  = (const float*)d_in[0];   // [B,S,H]
    const int*   pos = (const int*)  d_in[1];   // [B,S]
    const float* wp  = (const float*)d_in[2];   // [3H,H]
    const float* wo  = (const float*)d_in[3];   // [H,H]
    float* out = (float*)d_out;                 // [B,S,H]

    __half *qkv, *a16, *b16;
    cudaGetSymbolAddress((void**)&qkv, g_qkv);
    cudaGetSymbolAddress((void**)&a16, g_a16);
    cudaGetSymbolAddress((void**)&b16, g_b16);

    cudaFuncSetAttribute(gemm_f16<__half>, cudaFuncAttributeMaxDynamicSharedMemorySize, GEMM_SMEM);
    cudaFuncSetAttribute(gemm_f16<float>, cudaFuncAttributeMaxDynamicSharedMemorySize, GEMM_SMEM);
    cudaFuncSetAttribute(attn_mma, cudaFuncAttributeMaxDynamicSharedMemorySize, ATTN_SMEM);

    // 1. convert inputs to fp16
    conv_f16<<<(size_t)MTOK * NHID / 1024, 256>>>(hs, a16);
    conv_f16<<<(size_t)NQKV * NHID / 1024, 256>>>(wp, b16);

    // 2. QKV projection (fp16 tensor cores, 128x256 tiles) -> fp16 qkv
    gemm_f16<__half><<<dim3(MTOK / 128, NQKV / 256), 256, GEMM_SMEM>>>(
        a16, b16, qkv, MTOK, NQKV, NHID);

    // 3. RoPE (fp32 trig) -> head-major q (scaled by 1/sqrt(hd)*log2e), k
    rope_f16<<<NB * NS * NHEADS / 2, 128>>>(qkv, pos);

    // 4. Causal flash attention (fp16 HMMA, base-2 softmax); fp16 output
    attn_mma<<<dim3(NS / AQT, NB * NHEADS), 256, ATTN_SMEM>>>();

    // 5. output projection -> fp32 result
    conv_f16<<<(size_t)NHID * NHID / 1024, 256>>>(wo, b16);
    gemm_f16<float><<<dim3(MTOK / 128, NHID / 256), 256, GEMM_SMEM>>>(
        a16, b16, out, MTOK, NHID, NHID);
}

// round 13
// speedup vs baseline: 1.0546x; 1.0546x over previous
#include <cuda_runtime.h>
#include <cuda_bf16.h>
#include <cuda_fp16.h>
#include <math.h>
#include <stdint.h>

// Problem constants
#define NB 2
#define NS 2048
#define NHID 4096
#define NHEADS 32
#define HDIM 128
#define NQKV 12288   // 3*NHID
#define MTOK 4096    // NB*NS

// Scratch (device globals: allocation-free per harness rules)
__device__ __half g_qkv[(size_t)MTOK * NQKV];              // fp16; V read in-place
__device__ __half g_q16[(size_t)NB * NHEADS * NS * HDIM];  // head-major, q*scale*log2e
__device__ __half g_k16[(size_t)NB * NHEADS * NS * HDIM];
__device__ __half g_a16[(size_t)MTOK * NHID];              // GEMM A (fp16)
__device__ __half g_b16[(size_t)NQKV * NHID];              // GEMM B (fp16)

// ---------------------------------------------------------------------------
// Helpers (baseline PTX, valid on compute_100)
// ---------------------------------------------------------------------------
__device__ __forceinline__ uint32_t smem_u32(const void* p) {
    uint32_t a;
    asm("{ .reg .u64 t; cvta.to.shared.u64 t, %1; cvt.u32.u64 %0, t; }"
        : "=r"(a) : "l"(p));
    return a;
}

__device__ __forceinline__ void cp_async16(uint32_t dst, const void* src) {
    asm volatile("cp.async.cg.shared.global [%0], [%1], 16;" :: "r"(dst), "l"(src));
}
#define CP_COMMIT() asm volatile("cp.async.commit_group;" ::: "memory")

__device__ __forceinline__ void ldsm4(uint32_t* r, uint32_t addr) {
    asm volatile("ldmatrix.sync.aligned.m8n8.x4.shared.b16 {%0,%1,%2,%3}, [%4];"
                 : "=r"(r[0]), "=r"(r[1]), "=r"(r[2]), "=r"(r[3]) : "r"(addr));
}
__device__ __forceinline__ void ldsm4t(uint32_t* r, uint32_t addr) {
    asm volatile("ldmatrix.sync.aligned.m8n8.x4.trans.shared.b16 {%0,%1,%2,%3}, [%4];"
                 : "=r"(r[0]), "=r"(r[1]), "=r"(r[2]), "=r"(r[3]) : "r"(addr));
}

__device__ __forceinline__ void mma16816h(float* c, const uint32_t* a,
                                          uint32_t b0, uint32_t b1) {  // fp16
    asm volatile(
        "mma.sync.aligned.m16n8k16.row.col.f32.f16.f16.f32 "
        "{%0,%1,%2,%3}, {%4,%5,%6,%7}, {%8,%9}, {%0,%1,%2,%3};"
        : "+f"(c[0]), "+f"(c[1]), "+f"(c[2]), "+f"(c[3])
        : "r"(a[0]), "r"(a[1]), "r"(a[2]), "r"(a[3]), "r"(b0), "r"(b1));
}

#define SWZ(x) ((x) ^ (((x) >> 3) & 0x70))

__device__ __forceinline__ uint32_t pack_f16(float x, float y) {
    __half2 t = __floats2half2_rn(x, y);
    return *(uint32_t*)&t;
}

// ---------------------------------------------------------------------------
// convert: fp32 -> fp16
// ---------------------------------------------------------------------------
__global__ __launch_bounds__(256) void conv_f16(
    const float* __restrict__ x, __half* __restrict__ o)
{
    size_t i = ((size_t)blockIdx.x * 256 + threadIdx.x) * 4;
    float4 v = *(const float4*)(x + i);
    uint2 r;
    r.x = pack_f16(v.x, v.y);
    r.y = pack_f16(v.z, v.w);
    *(uint2*)(o + i) = r;
}

// ---------------------------------------------------------------------------
// fp16 single-pass GEMM (NT): C[m,n] = sum_k A[m,k]*B[n,k]
// CTA 128x128, 8 warps (2m x 4n), KTILE=64, 3-stage cp.async, 2 CTAs/SM.
// (R10 configuration — proven best; 128x256/1-CTA variant regressed.)
// ---------------------------------------------------------------------------
#define FKT 64
#define FBUF 16384                  // 128 rows x 128 B
#define FSTG (2 * FBUF)             // A + B per stage
#define GEMM_SMEM (3 * FSTG)        // 3 stages: 96 KB

template <typename OutT>
__global__ __launch_bounds__(256, 2) void gemm_f16(
    const __half* __restrict__ A, const __half* __restrict__ B,
    OutT* __restrict__ C, int M, int N, int K)
{
    extern __shared__ char smem[];
    const uint32_t sbase = smem_u32(smem);

    const int tid  = threadIdx.x;
    const int lane = tid & 31;
    const int wid  = tid >> 5;
    const int wm   = wid >> 2;
    const int wn   = wid & 3;
    const int m0   = blockIdx.x * 128;
    const int n0   = blockIdx.y * 128;

    auto load_stage = [&](int kt) {
        const int kk = kt * FKT;
        const uint32_t su = sbase + (kt % 3) * FSTG;
#pragma unroll
        for (int i = 0; i < 8; i++) {
            int c   = tid + 256 * i;        // 0..2047
            int op  = c >> 10;              // 0=A, 1=B
            int rem = c & 1023;
            int r   = rem >> 3;             // row 0..127
            int ch  = rem & 7;              // 16B chunk 0..7
            uint32_t dst = su + op * FBUF + SWZ((uint32_t)(r * 128 + ch * 16));
            const __half* src = op ? B : A;
            size_t gaddr = (size_t)((op ? n0 : m0) + r) * K + kk + ch * 8;
            cp_async16(dst, src + gaddr);
        }
        CP_COMMIT();
    };

    float acc[4][4][4];
#pragma unroll
    for (int i = 0; i < 4; i++)
#pragma unroll
        for (int j = 0; j < 4; j++)
#pragma unroll
            for (int v = 0; v < 4; v++) acc[i][j][v] = 0.f;

    const int KT = K / FKT;
    load_stage(0);
    load_stage(1);

    const int mat  = lane >> 3;
    const int rsub = (mat & 1) * 8 + (lane & 7);
    const int csub = mat >> 1;

    for (int kt = 0; kt < KT; kt++) {
        if (kt + 1 < KT) {
            asm volatile("cp.async.wait_group 1;" ::: "memory");
        } else {
            asm volatile("cp.async.wait_group 0;" ::: "memory");
        }
        __syncthreads();
        // Safe with 3 stages: load target (kt+2)%3 == (kt-1)%3, and every warp
        // passed the barrier above only after finishing compute(kt-1).
        if (kt + 2 < KT) load_stage(kt + 2);

        const uint32_t Ab = sbase + (kt % 3) * FSTG;
        const uint32_t Bb = Ab + FBUF;

#pragma unroll
        for (int ks = 0; ks < 4; ks++) {
            uint32_t af[4][4], bf[2][4];
            const int chh = ks * 2 + csub;
#pragma unroll
            for (int mf = 0; mf < 4; mf++) {
                int r = wm * 64 + mf * 16 + rsub;
                ldsm4(af[mf], Ab + SWZ((uint32_t)(r * 128 + chh * 16)));
            }
#pragma unroll
            for (int nf2 = 0; nf2 < 2; nf2++) {
                int r = wn * 32 + nf2 * 16 + rsub;
                ldsm4(bf[nf2], Bb + SWZ((uint32_t)(r * 128 + chh * 16)));
            }
#pragma unroll
            for (int mf = 0; mf < 4; mf++)
#pragma unroll
                for (int nf = 0; nf < 4; nf++)
                    mma16816h(acc[mf][nf], af[mf],
                              bf[nf >> 1][nf & 1], bf[nf >> 1][(nf & 1) + 2]);
        }
    }

    const int gg = lane >> 2;
    const int tq = lane & 3;
#pragma unroll
    for (int mf = 0; mf < 4; mf++) {
#pragma unroll
        for (int nf = 0; nf < 4; nf++) {
            int row = m0 + wm * 64 + mf * 16 + gg;
            int col = n0 + wn * 32 + nf * 8 + tq * 2;
            if (sizeof(OutT) == 4) {
                *(float2*)((float*)C + (size_t)row * N + col) =
                    make_float2(acc[mf][nf][0], acc[mf][nf][1]);
                *(float2*)((float*)C + (size_t)(row + 8) * N + col) =
                    make_float2(acc[mf][nf][2], acc[mf][nf][3]);
            } else {
                *(uint32_t*)((__half*)C + (size_t)row * N + col) =
                    pack_f16(acc[mf][nf][0], acc[mf][nf][1]);
                *(uint32_t*)((__half*)C + (size_t)(row + 8) * N + col) =
                    pack_f16(acc[mf][nf][2], acc[mf][nf][3]);
            }
        }
    }
}

// ---------------------------------------------------------------------------
// RoPE (fp32 trig) + head-major fp16 q (pre-scaled by 1/sqrt(hd)*log2(e)), k.
// V stays in g_qkv. 128 threads = 2 (token,head) pairs.
// ---------------------------------------------------------------------------
__global__ __launch_bounds__(128) void rope_f16(
    const __half* __restrict__ qkv, const int* __restrict__ positions)
{
    int t  = threadIdx.x;
    int gi = blockIdx.x * 2 + (t >> 6);   // (b*NS+s)*NHEADS+h
    int d  = t & 63;
    int h  = gi % NHEADS;
    int ms = gi / NHEADS;
    int s  = ms % NS;
    int b  = ms / NS;

    const __half* row = qkv + (size_t)ms * NQKV + h * HDIM;
    const float qscale = 0.12751745f;     // 1/sqrt(128) * log2(e)

    float posf = (float)positions[ms];
    // inv_freq = 10000^(-d/64) = 2^(-d * log2(10000)/64); exp2f is 1 MUFU
    float invf = exp2f(-(float)d * (13.287712379549449f / 64.0f));
    float sn, cs;
    sincosf(posf * invf, &sn, &cs);

    float q1 = __half2float(row[d]),        q2 = __half2float(row[d + 64]);
    float k1 = __half2float(row[NHID + d]), k2 = __half2float(row[NHID + d + 64]);

    size_t o = ((size_t)((b * NHEADS + h)) * NS + s) * HDIM + d;
    g_q16[o]      = __float2half_rn((q1 * cs - q2 * sn) * qscale);
    g_q16[o + 64] = __float2half_rn((q2 * cs + q1 * sn) * qscale);
    g_k16[o]      = __float2half_rn(k1 * cs - k2 * sn);
    g_k16[o + 64] = __float2half_rn(k2 * cs + k1 * sn);
}

// ---------------------------------------------------------------------------
// Flash attention, all-fp16 HMMA single-pass, base-2 softmax (Q pre-scaled by
// log2e so exp2f is a bare MUFU). CTA = 128 q-rows, 8 warps, 64-wide k chunks,
// 3-stage cp.async KV pipeline. V read directly from g_qkv. Heavy tiles first.
// ---------------------------------------------------------------------------
#define AQT 128
#define AKT 64
#define AKV 16384
#define ASTG (2 * AKV)                   // K | V per stage
#define ATTN_SMEM (32768 + 3 * ASTG)     // Q + 3 stages = 131072

__global__ __launch_bounds__(256, 1) void attn_mma()
{
    extern __shared__ char smem[];
    const uint32_t sQ = smem_u32(smem);
    const int tid  = threadIdx.x;
    const int lane = tid & 31;
    const int w    = tid >> 5;
    const int qt   = (int)gridDim.x - 1 - (int)blockIdx.x;  // heavy tiles first
    const int bh   = blockIdx.y;
    const int qs0  = qt * AQT;
    const size_t hb = (size_t)bh * NS * HDIM;
    const int b = bh >> 5, h = bh & 31;

    const int g  = lane >> 2;
    const int t2 = (lane & 3) * 2;
    const int lr = (lane & 7) + ((lane >> 3) & 1) * 8;
    const int lc = lane >> 4;

#pragma unroll
    for (int i = 0; i < 8; i++) {
        int idx = tid + 256 * i;
        int r = idx >> 4, c = idx & 15;
        uint32_t dst = sQ + r * 256 + ((c ^ (r & 7)) << 4);
        cp_async16(dst, g_q16 + hb + (size_t)(qs0 + r) * HDIM + c * 8);
    }
    auto load_kv = [&](int kt) {
        int kc0 = kt * AKT;
        uint32_t sb = sQ + 32768 + (kt % 3) * ASTG;
#pragma unroll
        for (int i = 0; i < 8; i++) {
            int idx = tid + 256 * i;             // 0..2047
            int buf = idx >> 10;                 // 0=K 1=V
            int rem = idx & 1023;
            int r = rem >> 4, c = rem & 15;
            uint32_t dst = sb + buf * AKV + r * 256 + ((c ^ (r & 7)) << 4);
            const void* src = buf == 0
                ? (const void*)(g_k16 + hb + (size_t)(kc0 + r) * HDIM + c * 8)
                : (const void*)(g_qkv + (size_t)(b * NS + kc0 + r) * NQKV
                                + 2 * NHID + h * HDIM + c * 8);
            cp_async16(dst, src);
        }
        CP_COMMIT();
    };

    const int KN = 2 * qt + 2;
    load_kv(0);
    load_kv(1);

    float oacc[16][4];
#pragma unroll
    for (int i = 0; i < 16; i++)
#pragma unroll
        for (int v = 0; v < 4; v++) oacc[i][v] = 0.f;
    float m0 = -INFINITY, m1 = -INFINITY, l0 = 0.f, l1 = 0.f;

    const int row0 = qs0 + w * 16 + g;

    for (int kt = 0; kt < KN; kt++) {
        if (kt + 1 < KN) {
            asm volatile("cp.async.wait_group 1;" ::: "memory");
        } else {
            asm volatile("cp.async.wait_group 0;" ::: "memory");
        }
        __syncthreads();
        if (kt + 2 < KN) load_kv(kt + 2);

        if (kt * AKT <= qs0 + w * 16 + 15) {
            const uint32_t sK = sQ + 32768 + (kt % 3) * ASTG;
            const uint32_t sV = sK + AKV;

            // ---- S = Q K^T (log2-scaled logits) ----
            float sacc[8][4];
#pragma unroll
            for (int nf = 0; nf < 8; nf++)
#pragma unroll
                for (int v = 0; v < 4; v++) sacc[nf][v] = 0.f;

#pragma unroll
            for (int ks = 0; ks < 8; ks++) {
                uint32_t aq[4];
                {
                    int r = w * 16 + lr, c = 2 * ks + lc;
                    ldsm4(aq, sQ + r * 256 + ((c ^ (r & 7)) << 4));
                }
                uint32_t kb4[4][4];
#pragma unroll
                for (int kg = 0; kg < 4; kg++) {
                    int r = kg * 16 + lr, c = 2 * ks + lc;
                    ldsm4(kb4[kg], sK + r * 256 + ((c ^ (r & 7)) << 4));
                }
#pragma unroll
                for (int nf = 0; nf < 8; nf++)
                    mma16816h(sacc[nf], aq, kb4[nf >> 1][nf & 1],
                              kb4[nf >> 1][(nf & 1) + 2]);
            }

            // ---- causal mask (diagonal chunks only) ----
            if (kt * AKT + 63 > qs0 + w * 16) {
#pragma unroll
                for (int nf = 0; nf < 8; nf++) {
                    int cb = kt * AKT + nf * 8 + t2;
                    if (cb     > row0)     sacc[nf][0] = -1e30f;
                    if (cb + 1 > row0)     sacc[nf][1] = -1e30f;
                    if (cb     > row0 + 8) sacc[nf][2] = -1e30f;
                    if (cb + 1 > row0 + 8) sacc[nf][3] = -1e30f;
                }
            }

            // ---- online softmax (base-2) ----
            float mx0 = -1e30f, mx1 = -1e30f;
#pragma unroll
            for (int nf = 0; nf < 8; nf++) {
                mx0 = fmaxf(mx0, fmaxf(sacc[nf][0], sacc[nf][1]));
                mx1 = fmaxf(mx1, fmaxf(sacc[nf][2], sacc[nf][3]));
            }
            mx0 = fmaxf(mx0, __shfl_xor_sync(0xffffffffu, mx0, 1));
            mx0 = fmaxf(mx0, __shfl_xor_sync(0xffffffffu, mx0, 2));
            mx1 = fmaxf(mx1, __shfl_xor_sync(0xffffffffu, mx1, 1));
            mx1 = fmaxf(mx1, __shfl_xor_sync(0xffffffffu, mx1, 2));

            float nm0 = fmaxf(m0, mx0), nm1 = fmaxf(m1, mx1);
            float cr0 = exp2f(m0 - nm0), cr1 = exp2f(m1 - nm1);
            m0 = nm0; m1 = nm1;
#pragma unroll
            for (int nf = 0; nf < 16; nf++) {
                oacc[nf][0] *= cr0; oacc[nf][1] *= cr0;
                oacc[nf][2] *= cr1; oacc[nf][3] *= cr1;
            }

            float rs0 = 0.f, rs1 = 0.f;
            uint32_t pf[4][4];
#pragma unroll
            for (int kg = 0; kg < 4; kg++) {
                float p[2][4];
#pragma unroll
                for (int j = 0; j < 2; j++) {
                    int nf = 2 * kg + j;
                    p[j][0] = exp2f(sacc[nf][0] - nm0);
                    p[j][1] = exp2f(sacc[nf][1] - nm0);
                    p[j][2] = exp2f(sacc[nf][2] - nm1);
                    p[j][3] = exp2f(sacc[nf][3] - nm1);
                    rs0 += p[j][0] + p[j][1];
                    rs1 += p[j][2] + p[j][3];
                }
                pf[kg][0] = pack_f16(p[0][0], p[0][1]);
                pf[kg][1] = pack_f16(p[0][2], p[0][3]);
                pf[kg][2] = pack_f16(p[1][0], p[1][1]);
                pf[kg][3] = pack_f16(p[1][2], p[1][3]);
            }
            rs0 += __shfl_xor_sync(0xffffffffu, rs0, 1);
            rs0 += __shfl_xor_sync(0xffffffffu, rs0, 2);
            rs1 += __shfl_xor_sync(0xffffffffu, rs1, 1);
            rs1 += __shfl_xor_sync(0xffffffffu, rs1, 2);
            l0 = l0 * cr0 + rs0;
            l1 = l1 * cr1 + rs1;

            // ---- O += P V (single fp16 pass) ----
#pragma unroll
            for (int dg = 0; dg < 8; dg++) {
#pragma unroll
                for (int kg = 0; kg < 4; kg++) {
                    int r = kg * 16 + lr, c = 2 * dg + lc;
                    uint32_t vv[4];
                    ldsm4t(vv, sV + (uint32_t)(r * 256 + ((c ^ (r & 7)) << 4)));
                    mma16816h(oacc[2 * dg],     pf[kg], vv[0], vv[1]);
                    mma16816h(oacc[2 * dg + 1], pf[kg], vv[2], vv[3]);
                }
            }
        }
        __syncthreads();
    }

    // epilogue: normalize, write fp16 into out-proj A buffer
    float inv0 = 1.f / l0, inv1 = 1.f / l1;
    size_t ob0 = (size_t)(b * NS + row0) * NHID + h * HDIM + t2;
    size_t ob1 = ob0 + (size_t)8 * NHID;
#pragma unroll
    for (int nf = 0; nf < 16; nf++) {
        *(uint32_t*)(g_a16 + ob0 + nf * 8) =
            pack_f16(oacc[nf][0] * inv0, oacc[nf][1] * inv0);
        *(uint32_t*)(g_a16 + ob1 + nf * 8) =
            pack_f16(oacc[nf][2] * inv1, oacc[nf][3] * inv1);
    }
}

// ---------------------------------------------------------------------------
// Launch
// ---------------------------------------------------------------------------
extern "C" void kernel_launch(void* const* d_in, const int* in_sizes, int n_in,
                              void* d_out, int out_size)
{
    const float* hs  = (const float*)d_in[0];   // [B,S,H]
    const int*   pos = (const int*)  d_in[1];   // [B,S]
    const float* wp  = (const float*)d_in[2];   // [3H,H]
    const float* wo  = (const float*)d_in[3];   // [H,H]
    float* out = (float*)d_out;                 // [B,S,H]

    __half *qkv, *a16, *b16;
    cudaGetSymbolAddress((void**)&qkv, g_qkv);
    cudaGetSymbolAddress((void**)&a16, g_a16);
    cudaGetSymbolAddress((void**)&b16, g_b16);

    cudaFuncSetAttribute(gemm_f16<__half>, cudaFuncAttributeMaxDynamicSharedMemorySize, GEMM_SMEM);
    cudaFuncSetAttribute(gemm_f16<float>, cudaFuncAttributeMaxDynamicSharedMemorySize, GEMM_SMEM);
    cudaFuncSetAttribute(attn_mma, cudaFuncAttributeMaxDynamicSharedMemorySize, ATTN_SMEM);

    // 1. convert inputs to fp16
    conv_f16<<<(size_t)MTOK * NHID / 1024, 256>>>(hs, a16);
    conv_f16<<<(size_t)NQKV * NHID / 1024, 256>>>(wp, b16);

    // 2. QKV projection (fp16 tensor cores, 128x128 tiles) -> fp16 qkv
    gemm_f16<__half><<<dim3(MTOK / 128, NQKV / 128), 256, GEMM_SMEM>>>(
        a16, b16, qkv, MTOK, NQKV, NHID);

    // 3. RoPE (fp32 trig) -> head-major q (scaled by 1/sqrt(hd)*log2e), k
    rope_f16<<<NB * NS * NHEADS / 2, 128>>>(qkv, pos);

    // 4. Causal flash attention (fp16 HMMA, base-2 softmax); fp16 output
    attn_mma<<<dim3(NS / AQT, NB * NHEADS), 256, ATTN_SMEM>>>();

    // 5. output projection -> fp32 result
    conv_f16<<<(size_t)NHID * NHID / 1024, 256>>>(wo, b16);
    gemm_f16<float><<<dim3(MTOK / 128, NHID / 128), 256, GEMM_SMEM>>>(
        a16, b16, out, MTOK, NHID, NHID);
}

// round 15
// speedup vs baseline: 1.0648x; 1.0097x over previous
#include <cuda_runtime.h>
#include <cuda_bf16.h>
#include <cuda_fp16.h>
#include <math.h>
#include <stdint.h>

// Problem constants
#define NB 2
#define NS 2048
#define NHID 4096
#define NHEADS 32
#define HDIM 128
#define NQKV 12288   // 3*NHID
#define MTOK 4096    // NB*NS

// Scratch (device globals: allocation-free per harness rules)
__device__ __half g_qkv[(size_t)MTOK * NQKV];              // only V region used
__device__ __half g_q16[(size_t)NB * NHEADS * NS * HDIM];  // head-major, q*scale*log2e
__device__ __half g_k16[(size_t)NB * NHEADS * NS * HDIM];
__device__ __half g_a16[(size_t)MTOK * NHID];              // GEMM A (fp16)
__device__ __half g_b16[(size_t)NQKV * NHID];              // GEMM B (fp16)

// ---------------------------------------------------------------------------
// Helpers (baseline PTX, valid on compute_100)
// ---------------------------------------------------------------------------
__device__ __forceinline__ uint32_t smem_u32(const void* p) {
    uint32_t a;
    asm("{ .reg .u64 t; cvta.to.shared.u64 t, %1; cvt.u32.u64 %0, t; }"
        : "=r"(a) : "l"(p));
    return a;
}

__device__ __forceinline__ void cp_async16(uint32_t dst, const void* src) {
    asm volatile("cp.async.cg.shared.global [%0], [%1], 16;" :: "r"(dst), "l"(src));
}
#define CP_COMMIT() asm volatile("cp.async.commit_group;" ::: "memory")

__device__ __forceinline__ void ldsm4(uint32_t* r, uint32_t addr) {
    asm volatile("ldmatrix.sync.aligned.m8n8.x4.shared.b16 {%0,%1,%2,%3}, [%4];"
                 : "=r"(r[0]), "=r"(r[1]), "=r"(r[2]), "=r"(r[3]) : "r"(addr));
}
__device__ __forceinline__ void ldsm4t(uint32_t* r, uint32_t addr) {
    asm volatile("ldmatrix.sync.aligned.m8n8.x4.trans.shared.b16 {%0,%1,%2,%3}, [%4];"
                 : "=r"(r[0]), "=r"(r[1]), "=r"(r[2]), "=r"(r[3]) : "r"(addr));
}

__device__ __forceinline__ void mma16816h(float* c, const uint32_t* a,
                                          uint32_t b0, uint32_t b1) {  // fp16
    asm volatile(
        "mma.sync.aligned.m16n8k16.row.col.f32.f16.f16.f32 "
        "{%0,%1,%2,%3}, {%4,%5,%6,%7}, {%8,%9}, {%0,%1,%2,%3};"
        : "+f"(c[0]), "+f"(c[1]), "+f"(c[2]), "+f"(c[3])
        : "r"(a[0]), "r"(a[1]), "r"(a[2]), "r"(a[3]), "r"(b0), "r"(b1));
}

#define SWZ(x) ((x) ^ (((x) >> 3) & 0x70))

__device__ __forceinline__ uint32_t pack_f16(float x, float y) {
    __half2 t = __floats2half2_rn(x, y);
    return *(uint32_t*)&t;
}

// ---------------------------------------------------------------------------
// convert: fp32 -> fp16
// ---------------------------------------------------------------------------
__global__ __launch_bounds__(256) void conv_f16(
    const float* __restrict__ x, __half* __restrict__ o)
{
    size_t i = ((size_t)blockIdx.x * 256 + threadIdx.x) * 4;
    float4 v = *(const float4*)(x + i);
    uint2 r;
    r.x = pack_f16(v.x, v.y);
    r.y = pack_f16(v.z, v.w);
    *(uint2*)(o + i) = r;
}

// ---------------------------------------------------------------------------
// Shared GEMM mainloop config (R10-proven: 128x128, 8 warps, KTILE=64,
// 3-stage cp.async, 2 CTAs/SM)
// ---------------------------------------------------------------------------
#define FKT 64
#define FBUF 16384                  // 128 rows x 128 B
#define FSTG (2 * FBUF)             // A + B per stage
#define GEMM_SMEM (3 * FSTG)        // 3 stages: 96 KB

#define GEMM_MAINLOOP(A_, B_, K_)                                              \
    float acc[4][4][4];                                                        \
    _Pragma("unroll")                                                          \
    for (int i = 0; i < 4; i++)                                                \
        _Pragma("unroll")                                                      \
        for (int j = 0; j < 4; j++)                                            \
            _Pragma("unroll")                                                  \
            for (int v = 0; v < 4; v++) acc[i][j][v] = 0.f;                    \
    const int KT = (K_) / FKT;                                                 \
    auto load_stage = [&](int kt) {                                            \
        const int kk = kt * FKT;                                               \
        const uint32_t su = sbase + (kt % 3) * FSTG;                           \
        _Pragma("unroll")                                                      \
        for (int i = 0; i < 8; i++) {                                          \
            int c   = tid + 256 * i;                                           \
            int op  = c >> 10;                                                 \
            int rem = c & 1023;                                                \
            int r   = rem >> 3;                                                \
            int ch  = rem & 7;                                                 \
            uint32_t dst = su + op * FBUF + SWZ((uint32_t)(r * 128 + ch * 16));\
            const __half* src = op ? (B_) : (A_);                              \
            size_t gaddr = (size_t)((op ? n0 : m0) + r) * (K_) + kk + ch * 8;  \
            cp_async16(dst, src + gaddr);                                      \
        }                                                                      \
        CP_COMMIT();                                                           \
    };                                                                         \
    load_stage(0);                                                             \
    load_stage(1);                                                             \
    const int mat  = lane >> 3;                                                \
    const int rsub = (mat & 1) * 8 + (lane & 7);                               \
    const int csub = mat >> 1;                                                 \
    for (int kt = 0; kt < KT; kt++) {                                          \
        if (kt + 1 < KT) {                                                     \
            asm volatile("cp.async.wait_group 1;" ::: "memory");               \
        } else {                                                               \
            asm volatile("cp.async.wait_group 0;" ::: "memory");               \
        }                                                                      \
        __syncthreads();                                                       \
        if (kt + 2 < KT) load_stage(kt + 2);                                   \
        const uint32_t Ab = sbase + (kt % 3) * FSTG;                           \
        const uint32_t Bb = Ab + FBUF;                                         \
        _Pragma("unroll")                                                      \
        for (int ks = 0; ks < 4; ks++) {                                       \
            uint32_t af[4][4], bf[2][4];                                       \
            const int chh = ks * 2 + csub;                                     \
            _Pragma("unroll")                                                  \
            for (int mf = 0; mf < 4; mf++) {                                   \
                int r = wm * 64 + mf * 16 + rsub;                              \
                ldsm4(af[mf], Ab + SWZ((uint32_t)(r * 128 + chh * 16)));       \
            }                                                                  \
            _Pragma("unroll")                                                  \
            for (int nf2 = 0; nf2 < 2; nf2++) {                                \
                int r = wn * 32 + nf2 * 16 + rsub;                             \
                ldsm4(bf[nf2], Bb + SWZ((uint32_t)(r * 128 + chh * 16)));      \
            }                                                                  \
            _Pragma("unroll")                                                  \
            for (int mf = 0; mf < 4; mf++)                                     \
                _Pragma("unroll")                                              \
                for (int nf = 0; nf < 4; nf++)                                 \
                    mma16816h(acc[mf][nf], af[mf],                             \
                              bf[nf >> 1][nf & 1], bf[nf >> 1][(nf & 1) + 2]); \
        }                                                                      \
    }

// ---------------------------------------------------------------------------
// out-projection GEMM (fp32 output)
// ---------------------------------------------------------------------------
__global__ __launch_bounds__(256, 2) void gemm_out(
    const __half* __restrict__ A, const __half* __restrict__ B,
    float* __restrict__ C, int M, int N, int K)
{
    extern __shared__ char smem[];
    const uint32_t sbase = smem_u32(smem);
    const int tid  = threadIdx.x;
    const int lane = tid & 31;
    const int wid  = tid >> 5;
    const int wm   = wid >> 2;
    const int wn   = wid & 3;
    const int m0   = blockIdx.x * 128;
    const int n0   = blockIdx.y * 128;

    GEMM_MAINLOOP(A, B, K)

    const int gg = lane >> 2;
    const int tq = lane & 3;
#pragma unroll
    for (int mf = 0; mf < 4; mf++) {
#pragma unroll
        for (int nf = 0; nf < 4; nf++) {
            int row = m0 + wm * 64 + mf * 16 + gg;
            int col = n0 + wn * 32 + nf * 8 + tq * 2;
            *(float2*)(C + (size_t)row * N + col) =
                make_float2(acc[mf][nf][0], acc[mf][nf][1]);
            *(float2*)(C + (size_t)(row + 8) * N + col) =
                make_float2(acc[mf][nf][2], acc[mf][nf][3]);
        }
    }
}

// ---------------------------------------------------------------------------
// QKV GEMM with fused RoPE epilogue.
// N-tile (128 cols) always lies in one region (q|k|v) and one head.
//   v tile : write fp16 directly into g_qkv (attention reads V there)
//   q/k    : stage fp32 tile in (dead) pipeline smem, apply fp32-sincos RoPE,
//            write head-major fp16 to g_q16 (pre-scaled log2e/sqrt(hd)) / g_k16.
// ---------------------------------------------------------------------------
__global__ __launch_bounds__(256, 2) void gemm_qkv(
    const __half* __restrict__ A, const __half* __restrict__ B,
    __half* __restrict__ C, const int* __restrict__ pos)
{
    extern __shared__ char smem[];
    const uint32_t sbase = smem_u32(smem);
    const int tid  = threadIdx.x;
    const int lane = tid & 31;
    const int wid  = tid >> 5;
    const int wm   = wid >> 2;
    const int wn   = wid & 3;
    const int m0   = blockIdx.x * 128;
    const int n0   = blockIdx.y * 128;

    GEMM_MAINLOOP(A, B, NHID)

    const int gg = lane >> 2;
    const int tq = lane & 3;
    const int region = n0 >> 12;            // 0=q 1=k 2=v
    const int h = (n0 & 4095) >> 7;         // head within region

    if (region == 2) {
        // V: direct fp16 write into g_qkv layout [ms][NQKV]
#pragma unroll
        for (int mf = 0; mf < 4; mf++) {
#pragma unroll
            for (int nf = 0; nf < 4; nf++) {
                int row = m0 + wm * 64 + mf * 16 + gg;
                int col = n0 + wn * 32 + nf * 8 + tq * 2;
                *(uint32_t*)(C + (size_t)row * NQKV + col) =
                    pack_f16(acc[mf][nf][0], acc[mf][nf][1]);
                *(uint32_t*)(C + (size_t)(row + 8) * NQKV + col) =
                    pack_f16(acc[mf][nf][2], acc[mf][nf][3]);
            }
        }
        return;
    }

    // q/k: stage tile to smem (pipeline buffers are dead after mainloop)
    __syncthreads();                        // all warps done with stage reads
    float* ts = (float*)smem;               // [128][132] fp32
#pragma unroll
    for (int mf = 0; mf < 4; mf++) {
#pragma unroll
        for (int nf = 0; nf < 4; nf++) {
            int row = wm * 64 + mf * 16 + gg;
            int col = wn * 32 + nf * 8 + tq * 2;
            ts[row * 132 + col]       = acc[mf][nf][0];
            ts[row * 132 + col + 1]   = acc[mf][nf][1];
            ts[(row + 8) * 132 + col]     = acc[mf][nf][2];
            ts[(row + 8) * 132 + col + 1] = acc[mf][nf][3];
        }
    }
    __syncthreads();

    __half* dst = (region == 0) ? g_q16 : g_k16;
    const float osc = (region == 0) ? 0.12751745f : 1.0f;  // log2e/sqrt(128)

#pragma unroll
    for (int i = 0; i < 16; i++) {
        int idx = tid + 256 * i;            // 0..4095 (pairs of rotation pairs)
        int r   = idx >> 5;                 // row 0..127
        int c2  = (idx & 31) * 2;           // d = c2, c2+1 in [0,64)
        float x1a = ts[r * 132 + c2],      x1b = ts[r * 132 + c2 + 1];
        float x2a = ts[r * 132 + c2 + 64], x2b = ts[r * 132 + c2 + 65];

        int ms = m0 + r;
        int s  = ms & (NS - 1);
        int b  = ms >> 11;                  // NS = 2048
        float posf = (float)pos[ms];
        // inv_freq(d) = 2^(-d * log2(10000)/64)
        float sa, ca, sb2, cb2;
        sincosf(posf * exp2f(-(float)c2 * (13.287712379549449f / 64.0f)), &sa, &ca);
        sincosf(posf * exp2f(-(float)(c2 + 1) * (13.287712379549449f / 64.0f)), &sb2, &cb2);

        float o1a = (x1a * ca - x2a * sa) * osc;
        float o2a = (x2a * ca + x1a * sa) * osc;
        float o1b = (x1b * cb2 - x2b * sb2) * osc;
        float o2b = (x2b * cb2 + x1b * sb2) * osc;

        size_t o = ((size_t)(b * NHEADS + h) * NS + s) * HDIM + c2;
        *(uint32_t*)(dst + o)      = pack_f16(o1a, o1b);
        *(uint32_t*)(dst + o + 64) = pack_f16(o2a, o2b);
    }
}

// ---------------------------------------------------------------------------
// Flash attention, all-fp16 HMMA single-pass, base-2 softmax. Unchanged from
// the passing R13 kernel.
// ---------------------------------------------------------------------------
#define AQT 128
#define AKT 64
#define AKV 16384
#define ASTG (2 * AKV)                   // K | V per stage
#define ATTN_SMEM (32768 + 3 * ASTG)     // Q + 3 stages = 131072

__global__ __launch_bounds__(256, 1) void attn_mma()
{
    extern __shared__ char smem[];
    const uint32_t sQ = smem_u32(smem);
    const int tid  = threadIdx.x;
    const int lane = tid & 31;
    const int w    = tid >> 5;
    const int qt   = (int)gridDim.x - 1 - (int)blockIdx.x;  // heavy tiles first
    const int bh   = blockIdx.y;
    const int qs0  = qt * AQT;
    const size_t hb = (size_t)bh * NS * HDIM;
    const int b = bh >> 5, h = bh & 31;

    const int g  = lane >> 2;
    const int t2 = (lane & 3) * 2;
    const int lr = (lane & 7) + ((lane >> 3) & 1) * 8;
    const int lc = lane >> 4;

#pragma unroll
    for (int i = 0; i < 8; i++) {
        int idx = tid + 256 * i;
        int r = idx >> 4, c = idx & 15;
        uint32_t dst = sQ + r * 256 + ((c ^ (r & 7)) << 4);
        cp_async16(dst, g_q16 + hb + (size_t)(qs0 + r) * HDIM + c * 8);
    }
    auto load_kv = [&](int kt) {
        int kc0 = kt * AKT;
        uint32_t sb = sQ + 32768 + (kt % 3) * ASTG;
#pragma unroll
        for (int i = 0; i < 8; i++) {
            int idx = tid + 256 * i;             // 0..2047
            int buf = idx >> 10;                 // 0=K 1=V
            int rem = idx & 1023;
            int r = rem >> 4, c = rem & 15;
            uint32_t dst = sb + buf * AKV + r * 256 + ((c ^ (r & 7)) << 4);
            const void* src = buf == 0
                ? (const void*)(g_k16 + hb + (size_t)(kc0 + r) * HDIM + c * 8)
                : (const void*)(g_qkv + (size_t)(b * NS + kc0 + r) * NQKV
                                + 2 * NHID + h * HDIM + c * 8);
            cp_async16(dst, src);
        }
        CP_COMMIT();
    };

    const int KN = 2 * qt + 2;
    load_kv(0);
    load_kv(1);

    float oacc[16][4];
#pragma unroll
    for (int i = 0; i < 16; i++)
#pragma unroll
        for (int v = 0; v < 4; v++) oacc[i][v] = 0.f;
    float m0 = -INFINITY, m1 = -INFINITY, l0 = 0.f, l1 = 0.f;

    const int row0 = qs0 + w * 16 + g;

    for (int kt = 0; kt < KN; kt++) {
        if (kt + 1 < KN) {
            asm volatile("cp.async.wait_group 1;" ::: "memory");
        } else {
            asm volatile("cp.async.wait_group 0;" ::: "memory");
        }
        __syncthreads();
        if (kt + 2 < KN) load_kv(kt + 2);

        if (kt * AKT <= qs0 + w * 16 + 15) {
            const uint32_t sK = sQ + 32768 + (kt % 3) * ASTG;
            const uint32_t sV = sK + AKV;

            // ---- S = Q K^T (log2-scaled logits) ----
            float sacc[8][4];
#pragma unroll
            for (int nf = 0; nf < 8; nf++)
#pragma unroll
                for (int v = 0; v < 4; v++) sacc[nf][v] = 0.f;

#pragma unroll
            for (int ks = 0; ks < 8; ks++) {
                uint32_t aq[4];
                {
                    int r = w * 16 + lr, c = 2 * ks + lc;
                    ldsm4(aq, sQ + r * 256 + ((c ^ (r & 7)) << 4));
                }
                uint32_t kb4[4][4];
#pragma unroll
                for (int kg = 0; kg < 4; kg++) {
                    int r = kg * 16 + lr, c = 2 * ks + lc;
                    ldsm4(kb4[kg], sK + r * 256 + ((c ^ (r & 7)) << 4));
                }
#pragma unroll
                for (int nf = 0; nf < 8; nf++)
                    mma16816h(sacc[nf], aq, kb4[nf >> 1][nf & 1],
                              kb4[nf >> 1][(nf & 1) + 2]);
            }

            // ---- causal mask (diagonal chunks only) ----
            if (kt * AKT + 63 > qs0 + w * 16) {
#pragma unroll
                for (int nf = 0; nf < 8; nf++) {
                    int cb = kt * AKT + nf * 8 + t2;
                    if (cb     > row0)     sacc[nf][0] = -1e30f;
                    if (cb + 1 > row0)     sacc[nf][1] = -1e30f;
                    if (cb     > row0 + 8) sacc[nf][2] = -1e30f;
                    if (cb + 1 > row0 + 8) sacc[nf][3] = -1e30f;
                }
            }

            // ---- online softmax (base-2) ----
            float mx0 = -1e30f, mx1 = -1e30f;
#pragma unroll
            for (int nf = 0; nf < 8; nf++) {
                mx0 = fmaxf(mx0, fmaxf(sacc[nf][0], sacc[nf][1]));
                mx1 = fmaxf(mx1, fmaxf(sacc[nf][2], sacc[nf][3]));
            }
            mx0 = fmaxf(mx0, __shfl_xor_sync(0xffffffffu, mx0, 1));
            mx0 = fmaxf(mx0, __shfl_xor_sync(0xffffffffu, mx0, 2));
            mx1 = fmaxf(mx1, __shfl_xor_sync(0xffffffffu, mx1, 1));
            mx1 = fmaxf(mx1, __shfl_xor_sync(0xffffffffu, mx1, 2));

            float nm0 = fmaxf(m0, mx0), nm1 = fmaxf(m1, mx1);
            float cr0 = exp2f(m0 - nm0), cr1 = exp2f(m1 - nm1);
            m0 = nm0; m1 = nm1;
#pragma unroll
            for (int nf = 0; nf < 16; nf++) {
                oacc[nf][0] *= cr0; oacc[nf][1] *= cr0;
                oacc[nf][2] *= cr1; oacc[nf][3] *= cr1;
            }

            float rs0 = 0.f, rs1 = 0.f;
            uint32_t pf[4][4];
#pragma unroll
            for (int kg = 0; kg < 4; kg++) {
                float p[2][4];
#pragma unroll
                for (int j = 0; j < 2; j++) {
                    int nf = 2 * kg + j;
                    p[j][0] = exp2f(sacc[nf][0] - nm0);
                    p[j][1] = exp2f(sacc[nf][1] - nm0);
                    p[j][2] = exp2f(sacc[nf][2] - nm1);
                    p[j][3] = exp2f(sacc[nf][3] - nm1);
                    rs0 += p[j][0] + p[j][1];
                    rs1 += p[j][2] + p[j][3];
                }
                pf[kg][0] = pack_f16(p[0][0], p[0][1]);
                pf[kg][1] = pack_f16(p[0][2], p[0][3]);
                pf[kg][2] = pack_f16(p[1][0], p[1][1]);
                pf[kg][3] = pack_f16(p[1][2], p[1][3]);
            }
            rs0 += __shfl_xor_sync(0xffffffffu, rs0, 1);
            rs0 += __shfl_xor_sync(0xffffffffu, rs0, 2);
            rs1 += __shfl_xor_sync(0xffffffffu, rs1, 1);
            rs1 += __shfl_xor_sync(0xffffffffu, rs1, 2);
            l0 = l0 * cr0 + rs0;
            l1 = l1 * cr1 + rs1;

            // ---- O += P V (single fp16 pass) ----
#pragma unroll
            for (int dg = 0; dg < 8; dg++) {
#pragma unroll
                for (int kg = 0; kg < 4; kg++) {
                    int r = kg * 16 + lr, c = 2 * dg + lc;
                    uint32_t vv[4];
                    ldsm4t(vv, sV + (uint32_t)(r * 256 + ((c ^ (r & 7)) << 4)));
                    mma16816h(oacc[2 * dg],     pf[kg], vv[0], vv[1]);
                    mma16816h(oacc[2 * dg + 1], pf[kg], vv[2], vv[3]);
                }
            }
        }
        __syncthreads();
    }

    // epilogue: normalize, write fp16 into out-proj A buffer
    float inv0 = 1.f / l0, inv1 = 1.f / l1;
    size_t ob0 = (size_t)(b * NS + row0) * NHID + h * HDIM + t2;
    size_t ob1 = ob0 + (size_t)8 * NHID;
#pragma unroll
    for (int nf = 0; nf < 16; nf++) {
        *(uint32_t*)(g_a16 + ob0 + nf * 8) =
            pack_f16(oacc[nf][0] * inv0, oacc[nf][1] * inv0);
        *(uint32_t*)(g_a16 + ob1 + nf * 8) =
            pack_f16(oacc[nf][2] * inv1, oacc[nf][3] * inv1);
    }
}

// ---------------------------------------------------------------------------
// Launch
// ---------------------------------------------------------------------------
extern "C" void kernel_launch(void* const* d_in, const int* in_sizes, int n_in,
                              void* d_out, int out_size)
{
    const float* hs  = (const float*)d_in[0];   // [B,S,H]
    const int*   pos = (const int*)  d_in[1];   // [B,S]
    const float* wp  = (const float*)d_in[2];   // [3H,H]
    const float* wo  = (const float*)d_in[3];   // [H,H]
    float* out = (float*)d_out;                 // [B,S,H]

    __half *qkv, *a16, *b16;
    cudaGetSymbolAddress((void**)&qkv, g_qkv);
    cudaGetSymbolAddress((void**)&a16, g_a16);
    cudaGetSymbolAddress((void**)&b16, g_b16);

    cudaFuncSetAttribute(gemm_qkv, cudaFuncAttributeMaxDynamicSharedMemorySize, GEMM_SMEM);
    cudaFuncSetAttribute(gemm_out, cudaFuncAttributeMaxDynamicSharedMemorySize, GEMM_SMEM);
    cudaFuncSetAttribute(attn_mma, cudaFuncAttributeMaxDynamicSharedMemorySize, ATTN_SMEM);

    // 1. convert inputs to fp16
    conv_f16<<<(size_t)MTOK * NHID / 1024, 256>>>(hs, a16);
    conv_f16<<<(size_t)NQKV * NHID / 1024, 256>>>(wp, b16);

    // 2. QKV projection with fused RoPE epilogue
    gemm_qkv<<<dim3(MTOK / 128, NQKV / 128), 256, GEMM_SMEM>>>(
        a16, b16, qkv, pos);

    // 3. Causal flash attention (fp16 HMMA, base-2 softmax); fp16 output
    attn_mma<<<dim3(NS / AQT, NB * NHEADS), 256, ATTN_SMEM>>>();

    // 4. output projection -> fp32 result
    conv_f16<<<(size_t)NHID * NHID / 1024, 256>>>(wo, b16);
    gemm_out<<<dim3(MTOK / 128, NHID / 128), 256, GEMM_SMEM>>>(
        a16, b16, out, MTOK, NHID, NHID);
}

// round 17
// speedup vs baseline: 1.0776x; 1.0120x over previous
#include <cuda_runtime.h>
#include <cuda_bf16.h>
#include <cuda_fp16.h>
#include <math.h>
#include <stdint.h>

// Problem constants
#define NB 2
#define NS 2048
#define NHID 4096
#define NHEADS 32
#define HDIM 128
#define NQKV 12288   // 3*NHID
#define MTOK 4096    // NB*NS

// Scratch (device globals: allocation-free per harness rules)
__device__ __half g_qkv[(size_t)MTOK * NQKV];              // only V region used
__device__ __half g_q16[(size_t)NB * NHEADS * NS * HDIM];  // head-major, q*scale*log2e
__device__ __half g_k16[(size_t)NB * NHEADS * NS * HDIM];
__device__ __half g_a16[(size_t)MTOK * NHID];              // GEMM A (fp16)
__device__ __half g_b16[(size_t)NQKV * NHID];              // GEMM B (fp16)

// ---------------------------------------------------------------------------
// Helpers (baseline PTX, valid on compute_100)
// ---------------------------------------------------------------------------
__device__ __forceinline__ uint32_t smem_u32(const void* p) {
    uint32_t a;
    asm("{ .reg .u64 t; cvta.to.shared.u64 t, %1; cvt.u32.u64 %0, t; }"
        : "=r"(a) : "l"(p));
    return a;
}

__device__ __forceinline__ void cp_async16(uint32_t dst, const void* src) {
    asm volatile("cp.async.cg.shared.global [%0], [%1], 16;" :: "r"(dst), "l"(src));
}
#define CP_COMMIT() asm volatile("cp.async.commit_group;" ::: "memory")

__device__ __forceinline__ void ldsm4(uint32_t* r, uint32_t addr) {
    asm volatile("ldmatrix.sync.aligned.m8n8.x4.shared.b16 {%0,%1,%2,%3}, [%4];"
                 : "=r"(r[0]), "=r"(r[1]), "=r"(r[2]), "=r"(r[3]) : "r"(addr));
}
__device__ __forceinline__ void ldsm4t(uint32_t* r, uint32_t addr) {
    asm volatile("ldmatrix.sync.aligned.m8n8.x4.trans.shared.b16 {%0,%1,%2,%3}, [%4];"
                 : "=r"(r[0]), "=r"(r[1]), "=r"(r[2]), "=r"(r[3]) : "r"(addr));
}

__device__ __forceinline__ void mma16816h(float* c, const uint32_t* a,
                                          uint32_t b0, uint32_t b1) {  // fp16
    asm volatile(
        "mma.sync.aligned.m16n8k16.row.col.f32.f16.f16.f32 "
        "{%0,%1,%2,%3}, {%4,%5,%6,%7}, {%8,%9}, {%0,%1,%2,%3};"
        : "+f"(c[0]), "+f"(c[1]), "+f"(c[2]), "+f"(c[3])
        : "r"(a[0]), "r"(a[1]), "r"(a[2]), "r"(a[3]), "r"(b0), "r"(b1));
}

#define SWZ(x) ((x) ^ (((x) >> 3) & 0x70))

__device__ __forceinline__ uint32_t pack_f16(float x, float y) {
    __half2 t = __floats2half2_rn(x, y);
    return *(uint32_t*)&t;
}

// ---------------------------------------------------------------------------
// convert: fp32 -> fp16
// ---------------------------------------------------------------------------
__global__ __launch_bounds__(256) void conv_f16(
    const float* __restrict__ x, __half* __restrict__ o)
{
    size_t i = ((size_t)blockIdx.x * 256 + threadIdx.x) * 4;
    float4 v = *(const float4*)(x + i);
    uint2 r;
    r.x = pack_f16(v.x, v.y);
    r.y = pack_f16(v.z, v.w);
    *(uint2*)(o + i) = r;
}

// ---------------------------------------------------------------------------
// Shared GEMM mainloop config (R10-proven: 128x128, 8 warps, KTILE=64,
// 3-stage cp.async, 2 CTAs/SM)
// ---------------------------------------------------------------------------
#define FKT 64
#define FBUF 16384                  // 128 rows x 128 B
#define FSTG (2 * FBUF)             // A + B per stage
#define GEMM_SMEM (3 * FSTG)        // 3 stages: 96 KB

#define GEMM_MAINLOOP(A_, B_, K_)                                              \
    float acc[4][4][4];                                                        \
    _Pragma("unroll")                                                          \
    for (int i = 0; i < 4; i++)                                                \
        _Pragma("unroll")                                                      \
        for (int j = 0; j < 4; j++)                                            \
            _Pragma("unroll")                                                  \
            for (int v = 0; v < 4; v++) acc[i][j][v] = 0.f;                    \
    const int KT = (K_) / FKT;                                                 \
    auto load_stage = [&](int kt) {                                            \
        const int kk = kt * FKT;                                               \
        const uint32_t su = sbase + (kt % 3) * FSTG;                           \
        _Pragma("unroll")                                                      \
        for (int i = 0; i < 8; i++) {                                          \
            int c   = tid + 256 * i;                                           \
            int op  = c >> 10;                                                 \
            int rem = c & 1023;                                                \
            int r   = rem >> 3;                                                \
            int ch  = rem & 7;                                                 \
            uint32_t dst = su + op * FBUF + SWZ((uint32_t)(r * 128 + ch * 16));\
            const __half* src = op ? (B_) : (A_);                              \
            size_t gaddr = (size_t)((op ? n0 : m0) + r) * (K_) + kk + ch * 8;  \
            cp_async16(dst, src + gaddr);                                      \
        }                                                                      \
        CP_COMMIT();                                                           \
    };                                                                         \
    load_stage(0);                                                             \
    load_stage(1);                                                             \
    const int mat  = lane >> 3;                                                \
    const int rsub = (mat & 1) * 8 + (lane & 7);                               \
    const int csub = mat >> 1;                                                 \
    for (int kt = 0; kt < KT; kt++) {                                          \
        if (kt + 1 < KT) {                                                     \
            asm volatile("cp.async.wait_group 1;" ::: "memory");               \
        } else {                                                               \
            asm volatile("cp.async.wait_group 0;" ::: "memory");               \
        }                                                                      \
        __syncthreads();                                                       \
        if (kt + 2 < KT) load_stage(kt + 2);                                   \
        const uint32_t Ab = sbase + (kt % 3) * FSTG;                           \
        const uint32_t Bb = Ab + FBUF;                                         \
        _Pragma("unroll")                                                      \
        for (int ks = 0; ks < 4; ks++) {                                       \
            uint32_t af[4][4], bf[2][4];                                       \
            const int chh = ks * 2 + csub;                                     \
            _Pragma("unroll")                                                  \
            for (int mf = 0; mf < 4; mf++) {                                   \
                int r = wm * 64 + mf * 16 + rsub;                              \
                ldsm4(af[mf], Ab + SWZ((uint32_t)(r * 128 + chh * 16)));       \
            }                                                                  \
            _Pragma("unroll")                                                  \
            for (int nf2 = 0; nf2 < 2; nf2++) {                                \
                int r = wn * 32 + nf2 * 16 + rsub;                             \
                ldsm4(bf[nf2], Bb + SWZ((uint32_t)(r * 128 + chh * 16)));      \
            }                                                                  \
            _Pragma("unroll")                                                  \
            for (int mf = 0; mf < 4; mf++)                                     \
                _Pragma("unroll")                                              \
                for (int nf = 0; nf < 4; nf++)                                 \
                    mma16816h(acc[mf][nf], af[mf],                             \
                              bf[nf >> 1][nf & 1], bf[nf >> 1][(nf & 1) + 2]); \
        }                                                                      \
    }

// ---------------------------------------------------------------------------
// out-projection GEMM (fp32 output)
// ---------------------------------------------------------------------------
__global__ __launch_bounds__(256, 2) void gemm_out(
    const __half* __restrict__ A, const __half* __restrict__ B,
    float* __restrict__ C, int M, int N, int K)
{
    extern __shared__ char smem[];
    const uint32_t sbase = smem_u32(smem);
    const int tid  = threadIdx.x;
    const int lane = tid & 31;
    const int wid  = tid >> 5;
    const int wm   = wid >> 2;
    const int wn   = wid & 3;
    const int m0   = blockIdx.x * 128;
    const int n0   = blockIdx.y * 128;

    GEMM_MAINLOOP(A, B, K)

    const int gg = lane >> 2;
    const int tq = lane & 3;
#pragma unroll
    for (int mf = 0; mf < 4; mf++) {
#pragma unroll
        for (int nf = 0; nf < 4; nf++) {
            int row = m0 + wm * 64 + mf * 16 + gg;
            int col = n0 + wn * 32 + nf * 8 + tq * 2;
            *(float2*)(C + (size_t)row * N + col) =
                make_float2(acc[mf][nf][0], acc[mf][nf][1]);
            *(float2*)(C + (size_t)(row + 8) * N + col) =
                make_float2(acc[mf][nf][2], acc[mf][nf][3]);
        }
    }
}

// ---------------------------------------------------------------------------
// QKV GEMM with fused RoPE epilogue (R15-proven).
// ---------------------------------------------------------------------------
__global__ __launch_bounds__(256, 2) void gemm_qkv(
    const __half* __restrict__ A, const __half* __restrict__ B,
    __half* __restrict__ C, const int* __restrict__ pos)
{
    extern __shared__ char smem[];
    const uint32_t sbase = smem_u32(smem);
    const int tid  = threadIdx.x;
    const int lane = tid & 31;
    const int wid  = tid >> 5;
    const int wm   = wid >> 2;
    const int wn   = wid & 3;
    const int m0   = blockIdx.x * 128;
    const int n0   = blockIdx.y * 128;

    GEMM_MAINLOOP(A, B, NHID)

    const int gg = lane >> 2;
    const int tq = lane & 3;
    const int region = n0 >> 12;            // 0=q 1=k 2=v
    const int h = (n0 & 4095) >> 7;         // head within region

    if (region == 2) {
#pragma unroll
        for (int mf = 0; mf < 4; mf++) {
#pragma unroll
            for (int nf = 0; nf < 4; nf++) {
                int row = m0 + wm * 64 + mf * 16 + gg;
                int col = n0 + wn * 32 + nf * 8 + tq * 2;
                *(uint32_t*)(C + (size_t)row * NQKV + col) =
                    pack_f16(acc[mf][nf][0], acc[mf][nf][1]);
                *(uint32_t*)(C + (size_t)(row + 8) * NQKV + col) =
                    pack_f16(acc[mf][nf][2], acc[mf][nf][3]);
            }
        }
        return;
    }

    __syncthreads();                        // all warps done with stage reads
    float* ts = (float*)smem;               // [128][132] fp32
#pragma unroll
    for (int mf = 0; mf < 4; mf++) {
#pragma unroll
        for (int nf = 0; nf < 4; nf++) {
            int row = wm * 64 + mf * 16 + gg;
            int col = wn * 32 + nf * 8 + tq * 2;
            ts[row * 132 + col]       = acc[mf][nf][0];
            ts[row * 132 + col + 1]   = acc[mf][nf][1];
            ts[(row + 8) * 132 + col]     = acc[mf][nf][2];
            ts[(row + 8) * 132 + col + 1] = acc[mf][nf][3];
        }
    }
    __syncthreads();

    __half* dst = (region == 0) ? g_q16 : g_k16;
    const float osc = (region == 0) ? 0.12751745f : 1.0f;  // log2e/sqrt(128)

#pragma unroll
    for (int i = 0; i < 16; i++) {
        int idx = tid + 256 * i;            // 0..4095
        int r   = idx >> 5;                 // row 0..127
        int c2  = (idx & 31) * 2;           // d = c2, c2+1 in [0,64)
        float x1a = ts[r * 132 + c2],      x1b = ts[r * 132 + c2 + 1];
        float x2a = ts[r * 132 + c2 + 64], x2b = ts[r * 132 + c2 + 65];

        int ms = m0 + r;
        int s  = ms & (NS - 1);
        int b  = ms >> 11;
        float posf = (float)pos[ms];
        float sa, ca, sb2, cb2;
        sincosf(posf * exp2f(-(float)c2 * (13.287712379549449f / 64.0f)), &sa, &ca);
        sincosf(posf * exp2f(-(float)(c2 + 1) * (13.287712379549449f / 64.0f)), &sb2, &cb2);

        float o1a = (x1a * ca - x2a * sa) * osc;
        float o2a = (x2a * ca + x1a * sa) * osc;
        float o1b = (x1b * cb2 - x2b * sb2) * osc;
        float o2b = (x2b * cb2 + x1b * sb2) * osc;

        size_t o = ((size_t)(b * NHEADS + h) * NS + s) * HDIM + c2;
        *(uint32_t*)(dst + o)      = pack_f16(o1a, o1b);
        *(uint32_t*)(dst + o + 64) = pack_f16(o2a, o2b);
    }
}

// ---------------------------------------------------------------------------
// Flash attention: AQT=64, 4 warps (128 threads), 2 CTAs/SM.
// Same per-warp math as R15 (16 rows/warp); two independent CTAs per SM
// overlap softmax (ALU/MUFU) of one with the MMA stream of the other.
// smem: Q 16 KB + 3 x 32 KB KV stages = 112 KB (fits 2/SM).
// ---------------------------------------------------------------------------
#define AQT 64
#define AKT 64
#define AKV 16384
#define ASTG (2 * AKV)                   // K | V per stage
#define ATTN_SMEM (16384 + 3 * ASTG)     // Q + 3 stages = 114688 (112 KB)

__global__ __launch_bounds__(128, 2) void attn_mma()
{
    extern __shared__ char smem[];
    const uint32_t sQ = smem_u32(smem);
    const int tid  = threadIdx.x;
    const int lane = tid & 31;
    const int w    = tid >> 5;              // 0..3
    const int qt   = (int)gridDim.x - 1 - (int)blockIdx.x;  // heavy tiles first
    const int bh   = blockIdx.y;
    const int qs0  = qt * AQT;
    const size_t hb = (size_t)bh * NS * HDIM;
    const int b = bh >> 5, h = bh & 31;

    const int g  = lane >> 2;
    const int t2 = (lane & 3) * 2;
    const int lr = (lane & 7) + ((lane >> 3) & 1) * 8;
    const int lc = lane >> 4;

    // Q tile: 64 rows x 128 d = 1024 16B chunks, 128 threads x 8
#pragma unroll
    for (int i = 0; i < 8; i++) {
        int idx = tid + 128 * i;
        int r = idx >> 4, c = idx & 15;
        uint32_t dst = sQ + r * 256 + ((c ^ (r & 7)) << 4);
        cp_async16(dst, g_q16 + hb + (size_t)(qs0 + r) * HDIM + c * 8);
    }
    auto load_kv = [&](int kt) {
        int kc0 = kt * AKT;
        uint32_t sb = sQ + 16384 + (kt % 3) * ASTG;
#pragma unroll
        for (int i = 0; i < 16; i++) {
            int idx = tid + 128 * i;             // 0..2047
            int buf = idx >> 10;                 // 0=K 1=V
            int rem = idx & 1023;
            int r = rem >> 4, c = rem & 15;
            uint32_t dst = sb + buf * AKV + r * 256 + ((c ^ (r & 7)) << 4);
            const void* src = buf == 0
                ? (const void*)(g_k16 + hb + (size_t)(kc0 + r) * HDIM + c * 8)
                : (const void*)(g_qkv + (size_t)(b * NS + kc0 + r) * NQKV
                                + 2 * NHID + h * HDIM + c * 8);
            cp_async16(dst, src);
        }
        CP_COMMIT();
    };

    const int KN = qt + 1;                   // 64-row q-tile covers qt+1 chunks
    load_kv(0);
    if (KN > 1) load_kv(1);

    float oacc[16][4];
#pragma unroll
    for (int i = 0; i < 16; i++)
#pragma unroll
        for (int v = 0; v < 4; v++) oacc[i][v] = 0.f;
    float m0 = -INFINITY, m1 = -INFINITY, l0 = 0.f, l1 = 0.f;

    const int row0 = qs0 + w * 16 + g;

    for (int kt = 0; kt < KN; kt++) {
        if (kt + 1 < KN) {
            asm volatile("cp.async.wait_group 1;" ::: "memory");
        } else {
            asm volatile("cp.async.wait_group 0;" ::: "memory");
        }
        __syncthreads();
        if (kt + 2 < KN) load_kv(kt + 2);

        if (kt * AKT <= qs0 + w * 16 + 15) {
            const uint32_t sK = sQ + 16384 + (kt % 3) * ASTG;
            const uint32_t sV = sK + AKV;

            // ---- S = Q K^T (log2-scaled logits) ----
            float sacc[8][4];
#pragma unroll
            for (int nf = 0; nf < 8; nf++)
#pragma unroll
                for (int v = 0; v < 4; v++) sacc[nf][v] = 0.f;

#pragma unroll
            for (int ks = 0; ks < 8; ks++) {
                uint32_t aq[4];
                {
                    int r = w * 16 + lr, c = 2 * ks + lc;
                    ldsm4(aq, sQ + r * 256 + ((c ^ (r & 7)) << 4));
                }
                uint32_t kb4[4][4];
#pragma unroll
                for (int kg = 0; kg < 4; kg++) {
                    int r = kg * 16 + lr, c = 2 * ks + lc;
                    ldsm4(kb4[kg], sK + r * 256 + ((c ^ (r & 7)) << 4));
                }
#pragma unroll
                for (int nf = 0; nf < 8; nf++)
                    mma16816h(sacc[nf], aq, kb4[nf >> 1][nf & 1],
                              kb4[nf >> 1][(nf & 1) + 2]);
            }

            // ---- causal mask (diagonal chunks only) ----
            if (kt * AKT + 63 > qs0 + w * 16) {
#pragma unroll
                for (int nf = 0; nf < 8; nf++) {
                    int cb = kt * AKT + nf * 8 + t2;
                    if (cb     > row0)     sacc[nf][0] = -1e30f;
                    if (cb + 1 > row0)     sacc[nf][1] = -1e30f;
                    if (cb     > row0 + 8) sacc[nf][2] = -1e30f;
                    if (cb + 1 > row0 + 8) sacc[nf][3] = -1e30f;
                }
            }

            // ---- online softmax (base-2) ----
            float mx0 = -1e30f, mx1 = -1e30f;
#pragma unroll
            for (int nf = 0; nf < 8; nf++) {
                mx0 = fmaxf(mx0, fmaxf(sacc[nf][0], sacc[nf][1]));
                mx1 = fmaxf(mx1, fmaxf(sacc[nf][2], sacc[nf][3]));
            }
            mx0 = fmaxf(mx0, __shfl_xor_sync(0xffffffffu, mx0, 1));
            mx0 = fmaxf(mx0, __shfl_xor_sync(0xffffffffu, mx0, 2));
            mx1 = fmaxf(mx1, __shfl_xor_sync(0xffffffffu, mx1, 1));
            mx1 = fmaxf(mx1, __shfl_xor_sync(0xffffffffu, mx1, 2));

            float nm0 = fmaxf(m0, mx0), nm1 = fmaxf(m1, mx1);
            float cr0 = exp2f(m0 - nm0), cr1 = exp2f(m1 - nm1);
            m0 = nm0; m1 = nm1;
#pragma unroll
            for (int nf = 0; nf < 16; nf++) {
                oacc[nf][0] *= cr0; oacc[nf][1] *= cr0;
                oacc[nf][2] *= cr1; oacc[nf][3] *= cr1;
            }

            float rs0 = 0.f, rs1 = 0.f;
            uint32_t pf[4][4];
#pragma unroll
            for (int kg = 0; kg < 4; kg++) {
                float p[2][4];
#pragma unroll
                for (int j = 0; j < 2; j++) {
                    int nf = 2 * kg + j;
                    p[j][0] = exp2f(sacc[nf][0] - nm0);
                    p[j][1] = exp2f(sacc[nf][1] - nm0);
                    p[j][2] = exp2f(sacc[nf][2] - nm1);
                    p[j][3] = exp2f(sacc[nf][3] - nm1);
                    rs0 += p[j][0] + p[j][1];
                    rs1 += p[j][2] + p[j][3];
                }
                pf[kg][0] = pack_f16(p[0][0], p[0][1]);
                pf[kg][1] = pack_f16(p[0][2], p[0][3]);
                pf[kg][2] = pack_f16(p[1][0], p[1][1]);
                pf[kg][3] = pack_f16(p[1][2], p[1][3]);
            }
            rs0 += __shfl_xor_sync(0xffffffffu, rs0, 1);
            rs0 += __shfl_xor_sync(0xffffffffu, rs0, 2);
            rs1 += __shfl_xor_sync(0xffffffffu, rs1, 1);
            rs1 += __shfl_xor_sync(0xffffffffu, rs1, 2);
            l0 = l0 * cr0 + rs0;
            l1 = l1 * cr1 + rs1;

            // ---- O += P V (single fp16 pass) ----
#pragma unroll
            for (int dg = 0; dg < 8; dg++) {
#pragma unroll
                for (int kg = 0; kg < 4; kg++) {
                    int r = kg * 16 + lr, c = 2 * dg + lc;
                    uint32_t vv[4];
                    ldsm4t(vv, sV + (uint32_t)(r * 256 + ((c ^ (r & 7)) << 4)));
                    mma16816h(oacc[2 * dg],     pf[kg], vv[0], vv[1]);
                    mma16816h(oacc[2 * dg + 1], pf[kg], vv[2], vv[3]);
                }
            }
        }
        __syncthreads();
    }

    // epilogue: normalize, write fp16 into out-proj A buffer
    float inv0 = 1.f / l0, inv1 = 1.f / l1;
    size_t ob0 = (size_t)(b * NS + row0) * NHID + h * HDIM + t2;
    size_t ob1 = ob0 + (size_t)8 * NHID;
#pragma unroll
    for (int nf = 0; nf < 16; nf++) {
        *(uint32_t*)(g_a16 + ob0 + nf * 8) =
            pack_f16(oacc[nf][0] * inv0, oacc[nf][1] * inv0);
        *(uint32_t*)(g_a16 + ob1 + nf * 8) =
            pack_f16(oacc[nf][2] * inv1, oacc[nf][3] * inv1);
    }
}

// ---------------------------------------------------------------------------
// Launch
// ---------------------------------------------------------------------------
extern "C" void kernel_launch(void* const* d_in, const int* in_sizes, int n_in,
                              void* d_out, int out_size)
{
    const float* hs  = (const float*)d_in[0];   // [B,S,H]
    const int*   pos = (const int*)  d_in[1];   // [B,S]
    const float* wp  = (const float*)d_in[2];   // [3H,H]
    const float* wo  = (const float*)d_in[3];   // [H,H]
    float* out = (float*)d_out;                 // [B,S,H]

    __half *qkv, *a16, *b16;
    cudaGetSymbolAddress((void**)&qkv, g_qkv);
    cudaGetSymbolAddress((void**)&a16, g_a16);
    cudaGetSymbolAddress((void**)&b16, g_b16);

    cudaFuncSetAttribute(gemm_qkv, cudaFuncAttributeMaxDynamicSharedMemorySize, GEMM_SMEM);
    cudaFuncSetAttribute(gemm_out, cudaFuncAttributeMaxDynamicSharedMemorySize, GEMM_SMEM);
    cudaFuncSetAttribute(attn_mma, cudaFuncAttributeMaxDynamicSharedMemorySize, ATTN_SMEM);

    // 1. convert inputs to fp16
    conv_f16<<<(size_t)MTOK * NHID / 1024, 256>>>(hs, a16);
    conv_f16<<<(size_t)NQKV * NHID / 1024, 256>>>(wp, b16);

    // 2. QKV projection with fused RoPE epilogue
    gemm_qkv<<<dim3(MTOK / 128, NQKV / 128), 256, GEMM_SMEM>>>(
        a16, b16, qkv, pos);

    // 3. Causal flash attention (fp16 HMMA, base-2 softmax, 2 CTAs/SM)
    attn_mma<<<dim3(NS / AQT, NB * NHEADS), 128, ATTN_SMEM>>>();

    // 4. output projection -> fp32 result
    conv_f16<<<(size_t)NHID * NHID / 1024, 256>>>(wo, b16);
    gemm_out<<<dim3(MTOK / 128, NHID / 128), 256, GEMM_SMEM>>>(
        a16, b16, out, MTOK, NHID, NHID);
}